// round 11
// baseline (speedup 1.0000x reference)
#include <cuda_runtime.h>

#define B_  128
#define A_  2048
#define C_  128
#define H_  512
#define S_  3
#define NR_ 2
#define PR_ 134                 // C + 3 + S
#define PW_ 390                 // 3C + 3 + S
#define NP_ (NR_*PR_ + PW_)     // 658 total params per batch row

// ---------------- scratch (device globals; no allocation allowed) ----------
__device__ float g_params[B_ * NP_];       // raw projections, [b][p]
__device__ float g_q[3 * B_ * C_];         // sigmoid(q) per head, [head][b][c]
__device__ float g_scal[3 * B_ * 8];       // qn, beta, gate, sw0..2, gamma
__device__ float g_sim[3 * B_ * A_];       // cosine sims
__device__ float g_w[3 * B_ * A_];         // final attention weights

__device__ __forceinline__ float sigmoidf_(float x) { return 1.f / (1.f + expf(-x)); }
__device__ __forceinline__ float softplusf_(float x) {
    return fmaxf(x, 0.f) + log1pf(expf(-fabsf(x)));
}

// ---------------- block reductions (256 threads) ---------------------------
__device__ __forceinline__ float blockSum256(float v, float* buf) {
    int t = threadIdx.x;
    #pragma unroll
    for (int o = 16; o; o >>= 1) v += __shfl_xor_sync(0xffffffffu, v, o);
    if ((t & 31) == 0) buf[t >> 5] = v;
    __syncthreads();
    if (t == 0) { float s = 0.f; for (int i = 0; i < 8; i++) s += buf[i]; buf[8] = s; }
    __syncthreads();
    float r = buf[8];
    __syncthreads();
    return r;
}
__device__ __forceinline__ float blockMax256(float v, float* buf) {
    int t = threadIdx.x;
    #pragma unroll
    for (int o = 16; o; o >>= 1) v = fmaxf(v, __shfl_xor_sync(0xffffffffu, v, o));
    if ((t & 31) == 0) buf[t >> 5] = v;
    __syncthreads();
    if (t == 0) { float s = buf[0]; for (int i = 1; i < 8; i++) s = fmaxf(s, buf[i]); buf[8] = s; }
    __syncthreads();
    float r = buf[8];
    __syncthreads();
    return r;
}

// ---------------- k_proj: [B,H] @ [H, NP]^T  (smem-tiled GEMM) --------------
// grid ceil(658/8)=83 blocks, 256 threads. Each block: 8 params x all 128 b.
__global__ void k_proj(const float* __restrict__ h,
                       const float* __restrict__ Wr, const float* __restrict__ br,
                       const float* __restrict__ Ww, const float* __restrict__ bw)
{
    __shared__ float hs[128 * 33];   // [b][kk] padded
    __shared__ float ws[8 * 33];     // [p_local][kk] padded
    int t = threadIdx.x;
    int pblk = blockIdx.x * 8;
    int p_l = t & 7, bs = t >> 3;    // bs in 0..31
    float acc0 = 0.f, acc1 = 0.f, acc2 = 0.f, acc3 = 0.f;

    for (int k0 = 0; k0 < H_; k0 += 32) {
        {   // weight tile: 8 rows x 32
            int pl = t >> 5, kk = t & 31;
            int p = pblk + pl;
            float v = 0.f;
            if (p < NP_) {
                const float* row = (p < NR_*PR_) ? (Wr + (size_t)p * H_)
                                                 : (Ww + (size_t)(p - NR_*PR_) * H_);
                v = row[k0 + kk];
            }
            ws[pl * 33 + kk] = v;
        }
        // h tile: 128 b x 32 k
        for (int x = t; x < 4096; x += 256) {
            int bb = x >> 5, kk = x & 31;
            hs[bb * 33 + kk] = h[bb * H_ + k0 + kk];
        }
        __syncthreads();
        #pragma unroll
        for (int kk = 0; kk < 32; kk++) {
            float w = ws[p_l * 33 + kk];
            acc0 = fmaf(hs[(bs      ) * 33 + kk], w, acc0);
            acc1 = fmaf(hs[(bs +  32) * 33 + kk], w, acc1);
            acc2 = fmaf(hs[(bs +  64) * 33 + kk], w, acc2);
            acc3 = fmaf(hs[(bs +  96) * 33 + kk], w, acc3);
        }
        __syncthreads();
    }
    int p = pblk + p_l;
    if (p < NP_) {
        float bias = (p < NR_*PR_) ? br[p] : bw[p - NR_*PR_];
        g_params[(bs      ) * NP_ + p] = acc0 + bias;
        g_params[(bs +  32) * NP_ + p] = acc1 + bias;
        g_params[(bs +  64) * NP_ + p] = acc2 + bias;
        g_params[(bs +  96) * NP_ + p] = acc3 + bias;
    }
}

// ---------------- k_prep: activations + per-head scalars --------------------
// grid B, 128 threads (thread = channel c)
__global__ void k_prep()
{
    __shared__ float red[8];
    int b = blockIdx.x, t = threadIdx.x;
    for (int head = 0; head < 3; head++) {
        int base = (head < 2) ? head * PR_ : NR_ * PR_;
        float raw = g_params[b * NP_ + base + t];
        float qv = sigmoidf_(raw);
        g_q[(head * B_ + b) * C_ + t] = qv;
        float ss = qv * qv;
        #pragma unroll
        for (int o = 16; o; o >>= 1) ss += __shfl_xor_sync(0xffffffffu, ss, o);
        if ((t & 31) == 0) red[t >> 5] = ss;
        __syncthreads();
        if (t == 0) {
            float s = red[0] + red[1] + red[2] + red[3];
            float* sc = g_scal + (head * B_ + b) * 8;
            sc[0] = fmaxf(sqrtf(s), 1e-8f);                         // |q|
            const float* pp = g_params + b * NP_ + base + C_;
            sc[1] = softplusf_(pp[0]) + 1.f;                        // beta
            sc[2] = sigmoidf_(pp[1]);                               // gate
            float s0 = pp[2], s1 = pp[3], s2 = pp[4];
            float mx = fmaxf(s0, fmaxf(s1, s2));
            float e0 = expf(s0 - mx), e1 = expf(s1 - mx), e2 = expf(s2 - mx);
            float iz = 1.f / (e0 + e1 + e2);
            sc[3] = e0 * iz; sc[4] = e1 * iz; sc[5] = e2 * iz;      // shift weights
            sc[6] = softplusf_(pp[5]) + 1.f;                        // gamma
        }
        __syncthreads();
    }
}

// ---------------- k_sim: cosine similarity, 3 heads, stream over mem --------
// grid B*64, 256 threads (8 warps). Warp handles 4 rows; lane = float4 chunk.
__global__ void k_sim(const float* __restrict__ mem)
{
    int bx   = blockIdx.x;
    int b    = bx >> 6;
    int a0   = (bx & 63) * 32;
    int warp = threadIdx.x >> 5, lane = threadIdx.x & 31;

    const float4* q0p = (const float4*)(g_q + (0 * B_ + b) * C_);
    const float4* q1p = (const float4*)(g_q + (1 * B_ + b) * C_);
    const float4* q2p = (const float4*)(g_q + (2 * B_ + b) * C_);
    float4 q0 = q0p[lane], q1 = q1p[lane], q2 = q2p[lane];
    float iqn0 = 1.f / g_scal[(0 * B_ + b) * 8];
    float iqn1 = 1.f / g_scal[(1 * B_ + b) * 8];
    float iqn2 = 1.f / g_scal[(2 * B_ + b) * 8];

    int a = a0 + warp * 4;
    const float4* m4 = (const float4*)mem + ((size_t)b * A_ + a) * 32;

    float nn[4], d0[4], d1[4], d2[4];
    #pragma unroll
    for (int j = 0; j < 4; j++) {
        float4 m = __ldcs(m4 + (size_t)j * 32 + lane);
        nn[j] = m.x*m.x + m.y*m.y + m.z*m.z + m.w*m.w;
        d0[j] = m.x*q0.x + m.y*q0.y + m.z*q0.z + m.w*q0.w;
        d1[j] = m.x*q1.x + m.y*q1.y + m.z*q1.z + m.w*q1.w;
        d2[j] = m.x*q2.x + m.y*q2.y + m.z*q2.z + m.w*q2.w;
    }
    #pragma unroll
    for (int j = 0; j < 4; j++) {
        #pragma unroll
        for (int o = 16; o; o >>= 1) {
            nn[j] += __shfl_xor_sync(0xffffffffu, nn[j], o);
            d0[j] += __shfl_xor_sync(0xffffffffu, d0[j], o);
            d1[j] += __shfl_xor_sync(0xffffffffu, d1[j], o);
            d2[j] += __shfl_xor_sync(0xffffffffu, d2[j], o);
        }
    }
    if (lane < 4) {
        int j  = lane;
        int aa = a + j;
        float imn = 1.f / fmaxf(sqrtf(nn[j]), 1e-8f);
        g_sim[((size_t)(0 * B_ + b)) * A_ + aa] = d0[j] * iqn0 * imn;
        g_sim[((size_t)(1 * B_ + b)) * A_ + aa] = d1[j] * iqn1 * imn;
        g_sim[((size_t)(2 * B_ + b)) * A_ + aa] = d2[j] * iqn2 * imn;
    }
}

// ---------------- k_addr: softmax + gate + shift + sharpen ------------------
// grid (B, 3), 256 threads. One block per (b, head) attention row.
__global__ void k_addr(const float* __restrict__ prev_ra,
                       const float* __restrict__ prev_wa)
{
    __shared__ float wg[A_];
    __shared__ float buf[16];
    int b = blockIdx.x, head = blockIdx.y, t = threadIdx.x;
    const float* sc = g_scal + (head * B_ + b) * 8;
    float beta = sc[1], gate = sc[2];
    float sw0 = sc[3], sw1 = sc[4], sw2 = sc[5], gamma = sc[6];

    const float* simrow = g_sim + ((size_t)(head * B_ + b)) * A_;
    float v[8];
    float mx = -1e30f;
    #pragma unroll
    for (int i = 0; i < 8; i++) { v[i] = simrow[t + i * 256]; mx = fmaxf(mx, v[i]); }
    mx = blockMax256(mx, buf);

    float s = 0.f;
    #pragma unroll
    for (int i = 0; i < 8; i++) { v[i] = expf(beta * (v[i] - mx)); s += v[i]; }
    float Z = blockSum256(s, buf);

    const float* prev = (head < 2) ? (prev_ra + ((size_t)(head * B_ + b)) * A_)
                                   : (prev_wa + (size_t)b * A_);
    float gz = gate / Z, og = 1.f - gate;
    #pragma unroll
    for (int i = 0; i < 8; i++) {
        int a = t + i * 256;
        wg[a] = gz * v[i] + og * prev[a];
    }
    __syncthreads();

    float p[8];
    float ps = 0.f;
    #pragma unroll
    for (int i = 0; i < 8; i++) {
        int a = t + i * 256;
        float wsa = wg[(a + 1) & (A_ - 1)] * sw0 + wg[a] * sw1 + wg[(a - 1) & (A_ - 1)] * sw2;
        p[i] = powf(wsa, gamma);
        ps += p[i];
    }
    float SP = blockSum256(ps, buf);
    float inv = 1.f / (SP + 1e-12f);
    float* wrow = g_w + ((size_t)(head * B_ + b)) * A_;
    #pragma unroll
    for (int i = 0; i < 8; i++) wrow[t + i * 256] = p[i] * inv;
}

// ---------------- k_zero: clear read_vectors region of d_out ----------------
__global__ void k_zero(float* __restrict__ out)
{
    out[blockIdx.x * 512 + threadIdx.x] = 0.f;
}

// ---------------- k_update: read_vectors + new_mem (single mem pass) --------
// grid B*32, 128 threads (thread = column c). 64 a-rows per block, unroll 8.
__global__ void k_update(const float* __restrict__ mem, float* __restrict__ out)
{
    __shared__ float wsm[3 * 64];
    int bx = blockIdx.x;
    int b  = bx >> 5;
    int a0 = (bx & 31) * 64;
    int t  = threadIdx.x;

    for (int k = t; k < 192; k += 128) {
        int head = k >> 6, aa = k & 63;
        wsm[k] = g_w[((size_t)(head * B_ + b)) * A_ + a0 + aa];
    }
    float ev = sigmoidf_(g_params[b * NP_ + NR_*PR_ +     C_ + 6 + t]);  // erase
    float av = sigmoidf_(g_params[b * NP_ + NR_*PR_ + 2 * C_ + 6 + t]);  // add
    __syncthreads();

    const float* mrow = mem + ((size_t)b * A_ + a0) * C_ + t;
    float* orow = out + (size_t)NR_ * B_ * C_ + ((size_t)b * A_ + a0) * C_ + t;

    float rv0 = 0.f, rv1 = 0.f;
    #pragma unroll 1
    for (int i = 0; i < 64; i += 8) {
        float m[8];
        #pragma unroll
        for (int j = 0; j < 8; j++) m[j] = __ldcs(mrow + (size_t)(i + j) * C_);
        #pragma unroll
        for (int j = 0; j < 8; j++) {
            float w0 = wsm[i + j], w1 = wsm[64 + i + j], w2 = wsm[128 + i + j];
            rv0 = fmaf(w0, m[j], rv0);
            rv1 = fmaf(w1, m[j], rv1);
            float keep = fmaf(-w2 * ev, 1.f, 1.f);            // 1 - w2*e
            __stcs(orow + (size_t)(i + j) * C_, fmaf(w2, av, m[j] * keep));
        }
    }
    atomicAdd(out + ((size_t)(0 * B_ + b)) * C_ + t, rv0);
    atomicAdd(out + ((size_t)(1 * B_ + b)) * C_ + t, rv1);
}

// ---------------- launch -----------------------------------------------------
extern "C" void kernel_launch(void* const* d_in, const int* in_sizes, int n_in,
                              void* d_out, int out_size)
{
    const float* h   = (const float*)d_in[0];   // [B,H]
    const float* mem = (const float*)d_in[1];   // [B,A,C]
    const float* pra = (const float*)d_in[2];   // [NR,B,A]
    const float* pwa = (const float*)d_in[3];   // [B,A]
    const float* Wr  = (const float*)d_in[4];   // [NR,PR,H]
    const float* br  = (const float*)d_in[5];   // [NR,PR]
    const float* Ww  = (const float*)d_in[6];   // [PW,H]
    const float* bw  = (const float*)d_in[7];   // [PW]
    float* out = (float*)d_out;                 // [NR*B*C + B*A*C]

    k_proj<<<(NP_ + 7) / 8, 256>>>(h, Wr, br, Ww, bw);
    k_prep<<<B_, 128>>>();
    k_sim<<<B_ * 64, 256>>>(mem);
    dim3 ga(B_, 3);
    k_addr<<<ga, 256>>>(pra, pwa);
    k_zero<<<64, 512>>>(out);
    k_update<<<B_ * 32, 128>>>(mem, out);
}

// round 12
// speedup vs baseline: 1.0023x; 1.0023x over previous
#include <cuda_runtime.h>

#define B_  128
#define A_  2048
#define C_  128
#define H_  512
#define S_  3
#define NR_ 2
#define PR_ 134                 // C + 3 + S
#define PW_ 390                 // 3C + 3 + S
#define NP_ (NR_*PR_ + PW_)     // 658 total params per batch row

// ---------------- scratch (device globals; no allocation allowed) ----------
__device__ float g_params[B_ * NP_];       // raw projections, [b][p]
__device__ float g_q[3 * B_ * C_];         // sigmoid(q) per head, [head][b][c]
__device__ float g_scal[3 * B_ * 8];       // qn, beta, gate, sw0..2, gamma
__device__ float g_sim[3 * B_ * A_];       // cosine sims
__device__ float g_w[3 * B_ * A_];         // final attention weights

__device__ __forceinline__ float sigmoidf_(float x) { return 1.f / (1.f + expf(-x)); }
__device__ __forceinline__ float softplusf_(float x) {
    return fmaxf(x, 0.f) + log1pf(expf(-fabsf(x)));
}

// ---------------- block reductions (256 threads) ---------------------------
__device__ __forceinline__ float blockSum256(float v, float* buf) {
    int t = threadIdx.x;
    #pragma unroll
    for (int o = 16; o; o >>= 1) v += __shfl_xor_sync(0xffffffffu, v, o);
    if ((t & 31) == 0) buf[t >> 5] = v;
    __syncthreads();
    if (t == 0) { float s = 0.f; for (int i = 0; i < 8; i++) s += buf[i]; buf[8] = s; }
    __syncthreads();
    float r = buf[8];
    __syncthreads();
    return r;
}
__device__ __forceinline__ float blockMax256(float v, float* buf) {
    int t = threadIdx.x;
    #pragma unroll
    for (int o = 16; o; o >>= 1) v = fmaxf(v, __shfl_xor_sync(0xffffffffu, v, o));
    if ((t & 31) == 0) buf[t >> 5] = v;
    __syncthreads();
    if (t == 0) { float s = buf[0]; for (int i = 1; i < 8; i++) s = fmaxf(s, buf[i]); buf[8] = s; }
    __syncthreads();
    float r = buf[8];
    __syncthreads();
    return r;
}

// ---------------- k_proj: [B,H] @ [H, NP]^T  (smem-tiled GEMM) --------------
// grid ceil(658/8)=83 blocks, 256 threads. Each block: 8 params x all 128 b.
__global__ void k_proj(const float* __restrict__ h,
                       const float* __restrict__ Wr, const float* __restrict__ br,
                       const float* __restrict__ Ww, const float* __restrict__ bw)
{
    __shared__ float hs[128 * 33];   // [b][kk] padded
    __shared__ float ws[8 * 33];     // [p_local][kk] padded
    int t = threadIdx.x;
    int pblk = blockIdx.x * 8;
    int p_l = t & 7, bs = t >> 3;    // bs in 0..31
    float acc0 = 0.f, acc1 = 0.f, acc2 = 0.f, acc3 = 0.f;

    for (int k0 = 0; k0 < H_; k0 += 32) {
        {   // weight tile: 8 rows x 32
            int pl = t >> 5, kk = t & 31;
            int p = pblk + pl;
            float v = 0.f;
            if (p < NP_) {
                const float* row = (p < NR_*PR_) ? (Wr + (size_t)p * H_)
                                                 : (Ww + (size_t)(p - NR_*PR_) * H_);
                v = row[k0 + kk];
            }
            ws[pl * 33 + kk] = v;
        }
        // h tile: 128 b x 32 k
        for (int x = t; x < 4096; x += 256) {
            int bb = x >> 5, kk = x & 31;
            hs[bb * 33 + kk] = h[bb * H_ + k0 + kk];
        }
        __syncthreads();
        #pragma unroll
        for (int kk = 0; kk < 32; kk++) {
            float w = ws[p_l * 33 + kk];
            acc0 = fmaf(hs[(bs      ) * 33 + kk], w, acc0);
            acc1 = fmaf(hs[(bs +  32) * 33 + kk], w, acc1);
            acc2 = fmaf(hs[(bs +  64) * 33 + kk], w, acc2);
            acc3 = fmaf(hs[(bs +  96) * 33 + kk], w, acc3);
        }
        __syncthreads();
    }
    int p = pblk + p_l;
    if (p < NP_) {
        float bias = (p < NR_*PR_) ? br[p] : bw[p - NR_*PR_];
        g_params[(bs      ) * NP_ + p] = acc0 + bias;
        g_params[(bs +  32) * NP_ + p] = acc1 + bias;
        g_params[(bs +  64) * NP_ + p] = acc2 + bias;
        g_params[(bs +  96) * NP_ + p] = acc3 + bias;
    }
}

// ---------------- k_prep: activations + per-head scalars --------------------
// grid B, 128 threads (thread = channel c)
__global__ void k_prep()
{
    __shared__ float red[8];
    int b = blockIdx.x, t = threadIdx.x;
    for (int head = 0; head < 3; head++) {
        int base = (head < 2) ? head * PR_ : NR_ * PR_;
        float raw = g_params[b * NP_ + base + t];
        float qv = sigmoidf_(raw);
        g_q[(head * B_ + b) * C_ + t] = qv;
        float ss = qv * qv;
        #pragma unroll
        for (int o = 16; o; o >>= 1) ss += __shfl_xor_sync(0xffffffffu, ss, o);
        if ((t & 31) == 0) red[t >> 5] = ss;
        __syncthreads();
        if (t == 0) {
            float s = red[0] + red[1] + red[2] + red[3];
            float* sc = g_scal + (head * B_ + b) * 8;
            sc[0] = fmaxf(sqrtf(s), 1e-8f);                         // |q|
            const float* pp = g_params + b * NP_ + base + C_;
            sc[1] = softplusf_(pp[0]) + 1.f;                        // beta
            sc[2] = sigmoidf_(pp[1]);                               // gate
            float s0 = pp[2], s1 = pp[3], s2 = pp[4];
            float mx = fmaxf(s0, fmaxf(s1, s2));
            float e0 = expf(s0 - mx), e1 = expf(s1 - mx), e2 = expf(s2 - mx);
            float iz = 1.f / (e0 + e1 + e2);
            sc[3] = e0 * iz; sc[4] = e1 * iz; sc[5] = e2 * iz;      // shift weights
            sc[6] = softplusf_(pp[5]) + 1.f;                        // gamma
        }
        __syncthreads();
    }
}

// ---------------- k_sim: cosine similarity, 3 heads, stream over mem --------
// grid B*64, 256 threads (8 warps). Warp handles 4 rows; lane = float4 chunk.
__global__ void k_sim(const float* __restrict__ mem)
{
    int bx   = blockIdx.x;
    int b    = bx >> 6;
    int a0   = (bx & 63) * 32;
    int warp = threadIdx.x >> 5, lane = threadIdx.x & 31;

    const float4* q0p = (const float4*)(g_q + (0 * B_ + b) * C_);
    const float4* q1p = (const float4*)(g_q + (1 * B_ + b) * C_);
    const float4* q2p = (const float4*)(g_q + (2 * B_ + b) * C_);
    float4 q0 = q0p[lane], q1 = q1p[lane], q2 = q2p[lane];
    float iqn0 = 1.f / g_scal[(0 * B_ + b) * 8];
    float iqn1 = 1.f / g_scal[(1 * B_ + b) * 8];
    float iqn2 = 1.f / g_scal[(2 * B_ + b) * 8];

    int a = a0 + warp * 4;
    const float4* m4 = (const float4*)mem + ((size_t)b * A_ + a) * 32;

    float nn[4], d0[4], d1[4], d2[4];
    #pragma unroll
    for (int j = 0; j < 4; j++) {
        float4 m = __ldcs(m4 + (size_t)j * 32 + lane);
        nn[j] = m.x*m.x + m.y*m.y + m.z*m.z + m.w*m.w;
        d0[j] = m.x*q0.x + m.y*q0.y + m.z*q0.z + m.w*q0.w;
        d1[j] = m.x*q1.x + m.y*q1.y + m.z*q1.z + m.w*q1.w;
        d2[j] = m.x*q2.x + m.y*q2.y + m.z*q2.z + m.w*q2.w;
    }
    #pragma unroll
    for (int j = 0; j < 4; j++) {
        #pragma unroll
        for (int o = 16; o; o >>= 1) {
            nn[j] += __shfl_xor_sync(0xffffffffu, nn[j], o);
            d0[j] += __shfl_xor_sync(0xffffffffu, d0[j], o);
            d1[j] += __shfl_xor_sync(0xffffffffu, d1[j], o);
            d2[j] += __shfl_xor_sync(0xffffffffu, d2[j], o);
        }
    }
    if (lane < 4) {
        int j  = lane;
        int aa = a + j;
        float imn = 1.f / fmaxf(sqrtf(nn[j]), 1e-8f);
        g_sim[((size_t)(0 * B_ + b)) * A_ + aa] = d0[j] * iqn0 * imn;
        g_sim[((size_t)(1 * B_ + b)) * A_ + aa] = d1[j] * iqn1 * imn;
        g_sim[((size_t)(2 * B_ + b)) * A_ + aa] = d2[j] * iqn2 * imn;
    }
}

// ---------------- k_addr: softmax + gate + shift + sharpen ------------------
// grid (B, 3), 256 threads. One block per (b, head) attention row.
__global__ void k_addr(const float* __restrict__ prev_ra,
                       const float* __restrict__ prev_wa)
{
    __shared__ float wg[A_];
    __shared__ float buf[16];
    int b = blockIdx.x, head = blockIdx.y, t = threadIdx.x;
    const float* sc = g_scal + (head * B_ + b) * 8;
    float beta = sc[1], gate = sc[2];
    float sw0 = sc[3], sw1 = sc[4], sw2 = sc[5], gamma = sc[6];

    const float* simrow = g_sim + ((size_t)(head * B_ + b)) * A_;
    float v[8];
    float mx = -1e30f;
    #pragma unroll
    for (int i = 0; i < 8; i++) { v[i] = simrow[t + i * 256]; mx = fmaxf(mx, v[i]); }
    mx = blockMax256(mx, buf);

    float s = 0.f;
    #pragma unroll
    for (int i = 0; i < 8; i++) { v[i] = expf(beta * (v[i] - mx)); s += v[i]; }
    float Z = blockSum256(s, buf);

    const float* prev = (head < 2) ? (prev_ra + ((size_t)(head * B_ + b)) * A_)
                                   : (prev_wa + (size_t)b * A_);
    float gz = gate / Z, og = 1.f - gate;
    #pragma unroll
    for (int i = 0; i < 8; i++) {
        int a = t + i * 256;
        wg[a] = gz * v[i] + og * prev[a];
    }
    __syncthreads();

    float p[8];
    float ps = 0.f;
    #pragma unroll
    for (int i = 0; i < 8; i++) {
        int a = t + i * 256;
        float wsa = wg[(a + 1) & (A_ - 1)] * sw0 + wg[a] * sw1 + wg[(a - 1) & (A_ - 1)] * sw2;
        p[i] = powf(wsa, gamma);
        ps += p[i];
    }
    float SP = blockSum256(ps, buf);
    float inv = 1.f / (SP + 1e-12f);
    float* wrow = g_w + ((size_t)(head * B_ + b)) * A_;
    #pragma unroll
    for (int i = 0; i < 8; i++) wrow[t + i * 256] = p[i] * inv;
}

// ---------------- k_zero: clear read_vectors region of d_out ----------------
__global__ void k_zero(float* __restrict__ out)
{
    out[blockIdx.x * 512 + threadIdx.x] = 0.f;
}

// ---------------- k_update: read_vectors + new_mem (single mem pass) --------
// grid B*32, 128 threads (thread = column c). 64 a-rows per block, unroll 8.
__global__ void k_update(const float* __restrict__ mem, float* __restrict__ out)
{
    __shared__ float wsm[3 * 64];
    int bx = blockIdx.x;
    int b  = bx >> 5;
    int a0 = (bx & 31) * 64;
    int t  = threadIdx.x;

    for (int k = t; k < 192; k += 128) {
        int head = k >> 6, aa = k & 63;
        wsm[k] = g_w[((size_t)(head * B_ + b)) * A_ + a0 + aa];
    }
    float ev = sigmoidf_(g_params[b * NP_ + NR_*PR_ +     C_ + 6 + t]);  // erase
    float av = sigmoidf_(g_params[b * NP_ + NR_*PR_ + 2 * C_ + 6 + t]);  // add
    __syncthreads();

    const float* mrow = mem + ((size_t)b * A_ + a0) * C_ + t;
    float* orow = out + (size_t)NR_ * B_ * C_ + ((size_t)b * A_ + a0) * C_ + t;

    float rv0 = 0.f, rv1 = 0.f;
    #pragma unroll 1
    for (int i = 0; i < 64; i += 8) {
        float m[8];
        #pragma unroll
        for (int j = 0; j < 8; j++) m[j] = __ldcs(mrow + (size_t)(i + j) * C_);
        #pragma unroll
        for (int j = 0; j < 8; j++) {
            float w0 = wsm[i + j], w1 = wsm[64 + i + j], w2 = wsm[128 + i + j];
            rv0 = fmaf(w0, m[j], rv0);
            rv1 = fmaf(w1, m[j], rv1);
            float keep = fmaf(-w2 * ev, 1.f, 1.f);            // 1 - w2*e
            __stcs(orow + (size_t)(i + j) * C_, fmaf(w2, av, m[j] * keep));
        }
    }
    atomicAdd(out + ((size_t)(0 * B_ + b)) * C_ + t, rv0);
    atomicAdd(out + ((size_t)(1 * B_ + b)) * C_ + t, rv1);
}

// ---------------- launch -----------------------------------------------------
extern "C" void kernel_launch(void* const* d_in, const int* in_sizes, int n_in,
                              void* d_out, int out_size)
{
    const float* h   = (const float*)d_in[0];   // [B,H]
    const float* mem = (const float*)d_in[1];   // [B,A,C]
    const float* pra = (const float*)d_in[2];   // [NR,B,A]
    const float* pwa = (const float*)d_in[3];   // [B,A]
    const float* Wr  = (const float*)d_in[4];   // [NR,PR,H]
    const float* br  = (const float*)d_in[5];   // [NR,PR]
    const float* Ww  = (const float*)d_in[6];   // [PW,H]
    const float* bw  = (const float*)d_in[7];   // [PW]
    float* out = (float*)d_out;                 // [NR*B*C + B*A*C]

    k_proj<<<(NP_ + 7) / 8, 256>>>(h, Wr, br, Ww, bw);
    k_prep<<<B_, 128>>>();
    k_sim<<<B_ * 64, 256>>>(mem);
    dim3 ga(B_, 3);
    k_addr<<<ga, 256>>>(pra, pwa);
    k_zero<<<64, 512>>>(out);
    k_update<<<B_ * 32, 128>>>(mem, out);
}